// round 3
// baseline (speedup 1.0000x reference)
#include <cuda_runtime.h>
#include <cstddef>

#define QSTEP      25.5f
#define INV_QSTEP  (1.0f / 25.5f)
#define DZ_OFF     (85.0f / 512.0f)
#define MAXV       1023.0f
#define INV_MAXV   (1.0f / 1023.0f)

#define WARPS_PER_BLOCK 4

__global__ void __launch_bounds__(WARPS_PER_BLOCK * 32)
vvc_dct_quant_idct_kernel(const float* __restrict__ x_g,
                          const float* __restrict__ C_g,
                          const float* __restrict__ cshift_g,
                          float* __restrict__ out_g)
{
    // Butterfly half-matrices.
    //  MeT[i][k] = C[2k][i],  MoT[i][k] = C[2k+1][i]   (forward form: a[k]=Σ_h C[k,h] r[h])
    //  Me [j][h] = C[2j][h],  Mo [j][h] = C[2j+1][h]   (transpose form: a[l]=Σ_w C[w,l] r[w])
    __shared__ __align__(16) float MeT[16][16];
    __shared__ __align__(16) float MoT[16][16];
    __shared__ __align__(16) float Me[16][16];
    __shared__ __align__(16) float Mo[16][16];
    __shared__ float csh[64];
    __shared__ __align__(16) float trbuf[WARPS_PER_BLOCK][33 * 32];

    const int tid  = threadIdx.x;
    const int warp = tid >> 5;
    const int lane = tid & 31;

    // C_g row-major: C_g[k*32+h] = C[k][h].
    for (int i = tid; i < 256; i += WARPS_PER_BLOCK * 32) {
        int a = i >> 4;          // 0..15
        int b = i & 15;          // 0..15
        MeT[a][b] = C_g[(2 * b) * 32 + a];       // C[2b][a]
        MoT[a][b] = C_g[(2 * b + 1) * 32 + a];   // C[2b+1][a]
        Me[a][b]  = C_g[(2 * a) * 32 + b];       // C[2a][b]
        Mo[a][b]  = C_g[(2 * a + 1) * 32 + b];   // C[2a+1][b]
    }
    if (tid < 64) csh[tid] = cshift_g[tid];
    __syncthreads();

    const int tile = blockIdx.x * WARPS_PER_BLOCK + warp;
    const float* __restrict__ xin  = x_g  + (size_t)tile * 1024;
    float*       __restrict__ xout = out_g + (size_t)tile * 1024;
    float* sh = trbuf[warp];

    float r[32];
    float a[32];

    // r[h] = X[h][lane] (coalesced), fold *1023.
#pragma unroll
    for (int h = 0; h < 32; h++)
        r[h] = xin[h * 32 + lane] * MAXV;

    // ======== Stage 1 (C ·): a[k] = Σ_h C[k,h] r[h] = (C X)[k][lane] ========
    {
        float s[16], d[16];
#pragma unroll
        for (int i = 0; i < 16; i++) { s[i] = r[i] + r[31 - i]; d[i] = r[i] - r[31 - i]; }
#pragma unroll
        for (int k = 0; k < 32; k++) a[k] = 0.0f;
#pragma unroll
        for (int i = 0; i < 16; i++) {
#pragma unroll
            for (int k = 0; k < 16; k++) {
                a[2 * k]     = fmaf(MeT[i][k], s[i], a[2 * k]);
                a[2 * k + 1] = fmaf(MoT[i][k], d[i], a[2 * k + 1]);
            }
        }
    }

    // transpose: thread gets row `lane` of tmp
    __syncwarp();
#pragma unroll
    for (int k = 0; k < 32; k++) sh[lane * 33 + k] = a[k];
    __syncwarp();
#pragma unroll
    for (int h = 0; h < 32; h++) r[h] = sh[h * 33 + lane];

    // ======== Stage 2 (· Cᵀ): a[l] = Σ_w C[l,w] r[w] = coeff[lane][l] ========
    {
        float s[16], d[16];
#pragma unroll
        for (int i = 0; i < 16; i++) { s[i] = r[i] + r[31 - i]; d[i] = r[i] - r[31 - i]; }
#pragma unroll
        for (int k = 0; k < 32; k++) a[k] = 0.0f;
#pragma unroll
        for (int i = 0; i < 16; i++) {
#pragma unroll
            for (int k = 0; k < 16; k++) {
                a[2 * k]     = fmaf(MeT[i][k], s[i], a[2 * k]);
                a[2 * k + 1] = fmaf(MoT[i][k], d[i], a[2 * k + 1]);
            }
        }
    }

    // ===== Pointwise: dead-zone quantize + coeff_shift dequant (STE forward) =====
#pragma unroll
    for (int k = 0; k < 32; k++) {
        float v   = a[k];
        float qa  = floorf(fabsf(v) * INV_QSTEP + DZ_OFF);   // q_abs (>= 0)
        int   idx = (int)qa;
        idx = idx < 63 ? idx : 63;
        float cs   = csh[idx];
        float corr = (qa < 64.0f) ? cs * (QSTEP / 1024.0f) : 0.0f;
        a[k] = copysignf(qa * QSTEP + corr, v);
    }

    // transpose: thread gets column `lane` of Q
    __syncwarp();
#pragma unroll
    for (int k = 0; k < 32; k++) sh[lane * 33 + k] = a[k];
    __syncwarp();
#pragma unroll
    for (int h = 0; h < 32; h++) r[h] = sh[h * 33 + lane];

    // ======== Stage 3 (C ·, per reference!): a[k] = Σ_h C[k,h] r[h] = tmp2[k][lane] ========
    {
        float s[16], d[16];
#pragma unroll
        for (int i = 0; i < 16; i++) { s[i] = r[i] + r[31 - i]; d[i] = r[i] - r[31 - i]; }
#pragma unroll
        for (int k = 0; k < 32; k++) a[k] = 0.0f;
#pragma unroll
        for (int i = 0; i < 16; i++) {
#pragma unroll
            for (int k = 0; k < 16; k++) {
                a[2 * k]     = fmaf(MeT[i][k], s[i], a[2 * k]);
                a[2 * k + 1] = fmaf(MoT[i][k], d[i], a[2 * k + 1]);
            }
        }
    }

    // transpose: thread gets row `lane` of tmp2
    __syncwarp();
#pragma unroll
    for (int k = 0; k < 32; k++) sh[lane * 33 + k] = a[k];
    __syncwarp();
#pragma unroll
    for (int h = 0; h < 32; h++) r[h] = sh[h * 33 + lane];

    // ======== Stage 4 (· C): a[l] = Σ_w C[w,l] r[w] = rec[lane][l] ========
    {
        float E[16], O[16];
#pragma unroll
        for (int h = 0; h < 16; h++) { E[h] = 0.0f; O[h] = 0.0f; }
#pragma unroll
        for (int j = 0; j < 16; j++) {
#pragma unroll
            for (int h = 0; h < 16; h++) {
                E[h] = fmaf(Me[j][h], r[2 * j],     E[h]);
                O[h] = fmaf(Mo[j][h], r[2 * j + 1], O[h]);
            }
        }
#pragma unroll
        for (int h = 0; h < 16; h++) { a[h] = E[h] + O[h]; a[31 - h] = E[h] - O[h]; }
    }

    // Final transpose for coalesced store, fold /1023.
    __syncwarp();
#pragma unroll
    for (int k = 0; k < 32; k++) sh[lane * 33 + k] = a[k];
    __syncwarp();
#pragma unroll
    for (int h = 0; h < 32; h++)
        xout[h * 32 + lane] = sh[h * 33 + lane] * INV_MAXV;
}

extern "C" void kernel_launch(void* const* d_in, const int* in_sizes, int n_in,
                              void* d_out, int out_size)
{
    const float* residual = (const float*)d_in[0];   // [256,64,32,32]
    const float* dct_mat  = (const float*)d_in[1];   // [32,32]
    const float* cshift   = (const float*)d_in[2];   // [64]
    float* out = (float*)d_out;

    const int n_tiles = in_sizes[0] / 1024;          // 16384
    const int blocks  = n_tiles / WARPS_PER_BLOCK;   // 4096

    vvc_dct_quant_idct_kernel<<<blocks, WARPS_PER_BLOCK * 32>>>(
        residual, dct_mat, cshift, out);
}

// round 4
// speedup vs baseline: 1.0034x; 1.0034x over previous
#include <cuda_runtime.h>
#include <cstddef>

#define QSTEP      25.5f
#define INV_QSTEP  (1.0f / 25.5f)
#define DZ_OFF     (85.0f / 512.0f)
#define MAXV       1023.0f
#define INV_MAXV   (1.0f / 1023.0f)

#define WARPS_PER_BLOCK 4

typedef unsigned long long u64;

__device__ __forceinline__ u64 pack2(float lo, float hi) {
    u64 v;
    asm("mov.b64 %0, {%1, %2};" : "=l"(v) : "f"(lo), "f"(hi));
    return v;
}
__device__ __forceinline__ void unpack2(u64 v, float& lo, float& hi) {
    asm("mov.b64 {%0, %1}, %2;" : "=f"(lo), "=f"(hi) : "l"(v));
}
__device__ __forceinline__ void fma2(u64& acc, u64 c, u64 m) {
    asm("fma.rn.f32x2 %0, %1, %2, %0;" : "+l"(acc) : "l"(c), "l"(m));
}

__global__ void __launch_bounds__(WARPS_PER_BLOCK * 32)
vvc_dct_quant_idct_kernel(const float* __restrict__ x_g,
                          const float* __restrict__ C_g,
                          const float* __restrict__ cshift_g,
                          float* __restrict__ out_g)
{
    // Single coefficient layout serving all stages:
    //   Ct[h*32 + k] = C[k][h]
    // Forward-form pairs:   (C[2k][i], C[2k+1][i])  = Ct[i*32 + 2k], Ct[i*32 + 2k+1]
    // Transpose-form pairs: (C[2j][h], C[2j+1][h])  = Ct[h*32 + 2j], Ct[h*32 + 2j+1]
    __shared__ __align__(16) float Ct[1024];
    __shared__ float csh[64];
    __shared__ __align__(16) float trbuf[WARPS_PER_BLOCK][33 * 32];

    const int tid  = threadIdx.x;
    const int warp = tid >> 5;
    const int lane = tid & 31;

    for (int i = tid; i < 1024; i += WARPS_PER_BLOCK * 32) {
        int k = i >> 5;
        int h = i & 31;
        Ct[h * 32 + k] = C_g[i];       // C_g[k*32+h] = C[k][h]
    }
    if (tid < 64) csh[tid] = cshift_g[tid];
    __syncthreads();

    const int tile = blockIdx.x * WARPS_PER_BLOCK + warp;
    const float* __restrict__ xin  = x_g  + (size_t)tile * 1024;
    float*       __restrict__ xout = out_g + (size_t)tile * 1024;
    float* sh = trbuf[warp];

    float r[32];
    float a[32];
    u64   acc[16];

    // r[h] = X[h][lane] (coalesced), fold *1023.
#pragma unroll
    for (int h = 0; h < 32; h++)
        r[h] = xin[h * 32 + lane] * MAXV;

    // ---- Forward-form stage macro: a[k] = Σ_h C[k,h] r[h] via even/odd butterfly,
    //      packed accumulators acc[k2] = (a[2k2], a[2k2+1]).
#define FWD_STAGE()                                                             \
    {                                                                           \
        _Pragma("unroll") for (int k2 = 0; k2 < 16; k2++) acc[k2] = 0ULL;       \
        _Pragma("unroll") for (int i = 0; i < 16; i++) {                        \
            u64 m2 = pack2(r[i] + r[31 - i], r[i] - r[31 - i]);                 \
            const ulonglong2* p = (const ulonglong2*)(Ct + i * 32);             \
            _Pragma("unroll") for (int k4 = 0; k4 < 8; k4++) {                  \
                ulonglong2 c = p[k4];                                           \
                fma2(acc[2 * k4],     c.x, m2);                                 \
                fma2(acc[2 * k4 + 1], c.y, m2);                                 \
            }                                                                   \
        }                                                                       \
        _Pragma("unroll") for (int k2 = 0; k2 < 16; k2++)                       \
            unpack2(acc[k2], a[2 * k2], a[2 * k2 + 1]);                         \
    }

#define TRANSPOSE()                                                             \
    {                                                                           \
        __syncwarp();                                                           \
        _Pragma("unroll") for (int k = 0; k < 32; k++) sh[lane * 33 + k] = a[k];\
        __syncwarp();                                                           \
        _Pragma("unroll") for (int h = 0; h < 32; h++) r[h] = sh[h * 33 + lane];\
    }

    // ======== Stage 1 (C ·): a[k] = (C X)[k][lane] ========
    FWD_STAGE();
    TRANSPOSE();

    // ======== Stage 2 (· Cᵀ): a[l] = coeff[lane][l] ========
    FWD_STAGE();

    // ===== Pointwise: dead-zone quantize + coeff_shift dequant (STE forward) =====
#pragma unroll
    for (int k = 0; k < 32; k++) {
        float v   = a[k];
        float qa  = floorf(fabsf(v) * INV_QSTEP + DZ_OFF);
        int   idx = (int)qa;
        idx = idx < 63 ? idx : 63;
        float cs   = csh[idx];
        float corr = (qa < 64.0f) ? cs * (QSTEP / 1024.0f) : 0.0f;
        a[k] = copysignf(qa * QSTEP + corr, v);
    }

    TRANSPOSE();

    // ======== Stage 3 (C ·, per reference): a[k] = (C Q)[k][lane] ========
    FWD_STAGE();
    TRANSPOSE();

    // ======== Stage 4 (· C): a[l] = Σ_w C[w,l] r[w], packed (E,O) butterfly ========
    {
        u64 rm2[16];
#pragma unroll
        for (int j = 0; j < 16; j++) rm2[j] = pack2(r[2 * j], r[2 * j + 1]);
#pragma unroll
        for (int h = 0; h < 16; h++) {
            u64 eo = 0ULL;
            const ulonglong2* p = (const ulonglong2*)(Ct + h * 32);
#pragma unroll
            for (int j2 = 0; j2 < 8; j2++) {
                ulonglong2 c = p[j2];
                fma2(eo, c.x, rm2[2 * j2]);
                fma2(eo, c.y, rm2[2 * j2 + 1]);
            }
            float E, O;
            unpack2(eo, E, O);
            a[h]      = E + O;
            a[31 - h] = E - O;
        }
    }

    // Final transpose for coalesced store, fold /1023.
    __syncwarp();
#pragma unroll
    for (int k = 0; k < 32; k++) sh[lane * 33 + k] = a[k];
    __syncwarp();
#pragma unroll
    for (int h = 0; h < 32; h++)
        xout[h * 32 + lane] = sh[h * 33 + lane] * INV_MAXV;

#undef FWD_STAGE
#undef TRANSPOSE
}

extern "C" void kernel_launch(void* const* d_in, const int* in_sizes, int n_in,
                              void* d_out, int out_size)
{
    const float* residual = (const float*)d_in[0];   // [256,64,32,32]
    const float* dct_mat  = (const float*)d_in[1];   // [32,32]
    const float* cshift   = (const float*)d_in[2];   // [64]
    float* out = (float*)d_out;

    const int n_tiles = in_sizes[0] / 1024;          // 16384
    const int blocks  = n_tiles / WARPS_PER_BLOCK;   // 4096

    vvc_dct_quant_idct_kernel<<<blocks, WARPS_PER_BLOCK * 32>>>(
        residual, dct_mat, cshift, out);
}